// round 1
// baseline (speedup 1.0000x reference)
#include <cuda_runtime.h>
#include <math_constants.h>

#define BN_EPS 1e-3f
#define NPTS 2048
#define NBATCH 8
#define NROWS (NPTS * NBATCH)

__device__ float g_xcat[NROWS * 512];
__device__ float g_ytop[NROWS * 256];
__device__ float g_ybot[NROWS * 256];
__device__ float g_sq[NROWS];
__device__ int   g_idx[NROWS * 16];

// ---------------------------------------------------------------------------
// squared norms per row
// ---------------------------------------------------------------------------
__global__ void sqnorm_kernel(const float* __restrict__ x, int lda, int C,
                              float* __restrict__ sq) {
    int i = blockIdx.x * blockDim.x + threadIdx.x;
    if (i < NROWS) {
        const float* p = x + (long long)i * lda;
        float s = 0.f;
        for (int c = 0; c < C; c++) { float v = p[c]; s = fmaf(v, v, s); }
        sq[i] = s;
    }
}

// ---------------------------------------------------------------------------
// kNN: per (32-row tile, batch) block. pd = 2*dot - sq_i - sq_j, top-16 by pd
// (ties -> lower index, matching jax.lax.top_k).
// ---------------------------------------------------------------------------
__global__ void knn_kernel(const float* __restrict__ x, int lda, int C,
                           const float* __restrict__ sq, int* __restrict__ outidx) {
    extern __shared__ float sm[];
    const int XI_S = 34, XJ_S = 68, PD_S = 68;
    int off = 0;
    float* xiT = sm;            off += ((C * XI_S + 3) & ~3);
    float* xjT = sm + off;      off += ((C * XJ_S + 3) & ~3);
    float* pd = sm + off;       off += 32 * PD_S;
    float* candv = sm + off;    off += 32 * 128;
    int* candi = (int*)(sm + off);

    const int rowbase = blockIdx.y * NPTS;
    const int i0 = blockIdx.x * 32;
    const int tid = threadIdx.x;

    // load xi tile transposed: xiT[c][i]
    for (int t = tid; t < 32 * C; t += 256) {
        int i = t / C, c = t - i * C;
        xiT[c * XI_S + i] = x[(long long)(rowbase + i0 + i) * lda + c];
    }

    const int ty = tid >> 4;   // 0..15 -> pair of i rows
    const int tx = tid & 15;   // 0..15 -> quad of j cols
    const float sqi0 = sq[rowbase + i0 + ty * 2];
    const float sqi1 = sq[rowbase + i0 + ty * 2 + 1];

    float v[16]; int id[16];
#pragma unroll
    for (int q = 0; q < 16; q++) { v[q] = -CUDART_INF_F; id[q] = 0x7fffffff; }
    float vmin = -CUDART_INF_F; int vminid = 0x7fffffff; int minpos = 0;

    const int r = tid >> 3, l = tid & 7;  // selection ownership: 8 lanes per row

    for (int jt = 0; jt < NPTS / 64; jt++) {
        const int j0 = jt * 64;
        __syncthreads();
        for (int t = tid; t < 64 * C; t += 256) {
            int j = t / C, c = t - j * C;
            xjT[c * XJ_S + j] = x[(long long)(rowbase + j0 + j) * lda + c];
        }
        __syncthreads();

        float a00 = 0, a01 = 0, a02 = 0, a03 = 0;
        float a10 = 0, a11 = 0, a12 = 0, a13 = 0;
        const float* xip = xiT + ty * 2;
        const float* xjp = xjT + tx * 4;
#pragma unroll 4
        for (int c = 0; c < C; c++) {
            float2 aa = *(const float2*)(xip + c * XI_S);
            float4 bb = *(const float4*)(xjp + c * XJ_S);
            a00 = fmaf(aa.x, bb.x, a00); a01 = fmaf(aa.x, bb.y, a01);
            a02 = fmaf(aa.x, bb.z, a02); a03 = fmaf(aa.x, bb.w, a03);
            a10 = fmaf(aa.y, bb.x, a10); a11 = fmaf(aa.y, bb.y, a11);
            a12 = fmaf(aa.y, bb.z, a12); a13 = fmaf(aa.y, bb.w, a13);
        }
        float sj0 = sq[rowbase + j0 + tx * 4 + 0];
        float sj1 = sq[rowbase + j0 + tx * 4 + 1];
        float sj2 = sq[rowbase + j0 + tx * 4 + 2];
        float sj3 = sq[rowbase + j0 + tx * 4 + 3];
        float4 r0 = make_float4(2.f * a00 - sqi0 - sj0, 2.f * a01 - sqi0 - sj1,
                                2.f * a02 - sqi0 - sj2, 2.f * a03 - sqi0 - sj3);
        float4 r1 = make_float4(2.f * a10 - sqi1 - sj0, 2.f * a11 - sqi1 - sj1,
                                2.f * a12 - sqi1 - sj2, 2.f * a13 - sqi1 - sj3);
        *(float4*)&pd[(ty * 2 + 0) * PD_S + tx * 4] = r0;
        *(float4*)&pd[(ty * 2 + 1) * PD_S + tx * 4] = r1;
        __syncthreads();

        // update per-thread top-16 (row r, 8 candidates)
#pragma unroll
        for (int s = 0; s < 8; s++) {
            int jj = l * 8 + s;
            float pv = pd[r * PD_S + jj];
            int jg = j0 + jj;
            if (pv > vmin || (pv == vmin && jg < vminid)) {
#pragma unroll
                for (int q = 0; q < 16; q++)
                    if (q == minpos) { v[q] = pv; id[q] = jg; }
                vmin = v[0]; vminid = id[0]; minpos = 0;
#pragma unroll
                for (int q = 1; q < 16; q++) {
                    bool w = (v[q] < vmin) || (v[q] == vmin && id[q] > vminid);
                    if (w) { vmin = v[q]; vminid = id[q]; minpos = q; }
                }
            }
        }
    }
    __syncthreads();
#pragma unroll
    for (int q = 0; q < 16; q++) {
        candv[r * 128 + l * 16 + q] = v[q];
        candi[r * 128 + l * 16 + q] = id[q];
    }
    __syncthreads();
    if (tid < 32) {
        const int rr = tid;
        float* cv = candv + rr * 128;
        int* ci = candi + rr * 128;
        for (int t = 0; t < 16; t++) {
            float bv = -CUDART_INF_F; int bj = 0x7fffffff; int bs = 0;
            for (int s2 = 0; s2 < 128; s2++) {
                float c2 = cv[s2]; int j2 = ci[s2];
                if (c2 > bv || (c2 == bv && j2 < bj)) { bv = c2; bj = j2; bs = s2; }
            }
            cv[bs] = -CUDART_INF_F; ci[bs] = 0x7fffffff;
            outidx[(long long)(rowbase + i0 + rr) * 16 + t] = bj;
        }
    }
}

// ---------------------------------------------------------------------------
// SGEMM 64x64x16 tiles, 256 threads, 4x4 micro-tile. Optional fused BN+ReLU.
// C[m,n] = sum_k A[m*lda+k] * B[k*ldb+n]
// ---------------------------------------------------------------------------
__global__ void sgemm_kernel(const float* __restrict__ A, int lda,
                             const float* __restrict__ B, int ldb,
                             float* __restrict__ Co, int ldc, int K,
                             const float* __restrict__ bg, const float* __restrict__ bb,
                             const float* __restrict__ bm, const float* __restrict__ bvv) {
    __shared__ float As[16 * 68];
    __shared__ float Bs[16 * 68];
    const int mb = blockIdx.y * 64, nb = blockIdx.x * 64;
    const int tid = threadIdx.x;
    const int ry = tid >> 4, rx = tid & 15;
    float acc[4][4] = {};

    for (int kt = 0; kt < K; kt += 16) {
#pragma unroll
        for (int t = tid; t < 1024; t += 256) {
            int m = t >> 4, k = t & 15;
            As[k * 68 + m] = (kt + k < K) ? A[(long long)(mb + m) * lda + kt + k] : 0.f;
        }
#pragma unroll
        for (int t = tid; t < 1024; t += 256) {
            int k = t >> 6, n = t & 63;
            Bs[k * 68 + n] = (kt + k < K) ? B[(long long)(kt + k) * ldb + nb + n] : 0.f;
        }
        __syncthreads();
#pragma unroll
        for (int k = 0; k < 16; k++) {
            float4 a = *(const float4*)&As[k * 68 + ry * 4];
            float4 bq = *(const float4*)&Bs[k * 68 + rx * 4];
            acc[0][0] = fmaf(a.x, bq.x, acc[0][0]); acc[0][1] = fmaf(a.x, bq.y, acc[0][1]);
            acc[0][2] = fmaf(a.x, bq.z, acc[0][2]); acc[0][3] = fmaf(a.x, bq.w, acc[0][3]);
            acc[1][0] = fmaf(a.y, bq.x, acc[1][0]); acc[1][1] = fmaf(a.y, bq.y, acc[1][1]);
            acc[1][2] = fmaf(a.y, bq.z, acc[1][2]); acc[1][3] = fmaf(a.y, bq.w, acc[1][3]);
            acc[2][0] = fmaf(a.z, bq.x, acc[2][0]); acc[2][1] = fmaf(a.z, bq.y, acc[2][1]);
            acc[2][2] = fmaf(a.z, bq.z, acc[2][2]); acc[2][3] = fmaf(a.z, bq.w, acc[2][3]);
            acc[3][0] = fmaf(a.w, bq.x, acc[3][0]); acc[3][1] = fmaf(a.w, bq.y, acc[3][1]);
            acc[3][2] = fmaf(a.w, bq.z, acc[3][2]); acc[3][3] = fmaf(a.w, bq.w, acc[3][3]);
        }
        __syncthreads();
    }
    if (bg) {
#pragma unroll
        for (int j = 0; j < 4; j++) {
            int n = nb + rx * 4 + j;
            float s = bg[n] * rsqrtf(bvv[n] + BN_EPS);
            float t = bb[n] - bm[n] * s;
#pragma unroll
            for (int i = 0; i < 4; i++) acc[i][j] = fmaxf(fmaf(acc[i][j], s, t), 0.f);
        }
    }
#pragma unroll
    for (int i = 0; i < 4; i++) {
        *(float4*)&Co[(long long)(mb + ry * 4 + i) * ldc + nb + rx * 4] =
            make_float4(acc[i][0], acc[i][1], acc[i][2], acc[i][3]);
    }
}

// ---------------------------------------------------------------------------
// gather + BN + ReLU + max over k=16 neighbors
// ---------------------------------------------------------------------------
__global__ void gathermax_kernel(const float* __restrict__ ytop, const float* __restrict__ ybot,
                                 const int* __restrict__ idx, int D,
                                 const float* __restrict__ g, const float* __restrict__ b,
                                 const float* __restrict__ m, const float* __restrict__ vv,
                                 float* __restrict__ out, int ldo) {
    const int mrow = blockIdx.x;
    const int base = (mrow >> 11) << 11;  // batch start (NPTS = 2048)
    __shared__ int sid[16];
    if (threadIdx.x < 16) sid[threadIdx.x] = idx[mrow * 16 + threadIdx.x];
    __syncthreads();
    for (int d = threadIdx.x; d < D; d += blockDim.x) {
        float s = g[d] * rsqrtf(vv[d] + BN_EPS);
        float t = b[d] - m[d] * s;
        float top = ytop[(long long)mrow * D + d];
        float best = -CUDART_INF_F;
#pragma unroll
        for (int kk = 0; kk < 16; kk++) {
            float yb = ybot[(long long)(base + sid[kk]) * D + d];
            float h = fmaf(top + yb, s, t);
            best = fmaxf(best, h);
        }
        out[(long long)mrow * ldo + d] = fmaxf(best, 0.f);
    }
}

// ---------------------------------------------------------------------------
extern "C" void kernel_launch(void* const* d_in, const int* in_sizes, int n_in,
                              void* d_out, int out_size) {
    const float* x = (const float*)d_in[0];
    const float *W[5], *gg[5], *bb[5], *mm[5], *vv[5];
    for (int i = 0; i < 5; i++) {
        W[i]  = (const float*)d_in[1 + 5 * i];
        gg[i] = (const float*)d_in[2 + 5 * i];
        bb[i] = (const float*)d_in[3 + 5 * i];
        mm[i] = (const float*)d_in[4 + 5 * i];
        vv[i] = (const float*)d_in[5 + 5 * i];
    }
    float *xcat, *ytop, *ybot, *sqp; int* idxp;
    cudaGetSymbolAddress((void**)&xcat, g_xcat);
    cudaGetSymbolAddress((void**)&ytop, g_ytop);
    cudaGetSymbolAddress((void**)&ybot, g_ybot);
    cudaGetSymbolAddress((void**)&sqp, g_sq);
    cudaGetSymbolAddress((void**)&idxp, g_idx);

    cudaFuncSetAttribute(knn_kernel, cudaFuncAttributeMaxDynamicSharedMemorySize, 150000);

    const int Cs[4] = {3, 64, 64, 128};
    const int Ds[4] = {64, 64, 128, 256};
    const float* in = x;
    int lda = 3;
    int coloff = 0;
    for (int s = 0; s < 4; s++) {
        const int C = Cs[s], D = Ds[s];
        sqnorm_kernel<<<NROWS / 256, 256>>>(in, lda, C, sqp);
        size_t smem = (size_t)(((C * 34 + 3) & ~3) + ((C * 68 + 3) & ~3) +
                               32 * 68 + 32 * 128 + 32 * 128) * 4;
        knn_kernel<<<dim3(NPTS / 32, NBATCH), 256, smem>>>(in, lda, C, sqp, idxp);
        dim3 gdim(D / 64, NROWS / 64);
        sgemm_kernel<<<gdim, 256>>>(in, lda, W[s], D, ytop, D, C,
                                    nullptr, nullptr, nullptr, nullptr);
        sgemm_kernel<<<gdim, 256>>>(in, lda, W[s] + (long long)C * D, D, ybot, D, C,
                                    nullptr, nullptr, nullptr, nullptr);
        float* outp = xcat + coloff;
        gathermax_kernel<<<NROWS, 128>>>(ytop, ybot, idxp, D,
                                         gg[s], bb[s], mm[s], vv[s], outp, 512);
        in = outp; lda = 512;
        coloff += D;
    }
    // final: relu(bn(xcat @ W5)) -> d_out
    sgemm_kernel<<<dim3(512 / 64, NROWS / 64), 256>>>(xcat, 512, W[4], 512,
                                                      (float*)d_out, 512, 512,
                                                      gg[4], bb[4], mm[4], vv[4]);
}